// round 1
// baseline (speedup 1.0000x reference)
#include <cuda_runtime.h>

// Problem constants (fixed by the dataset: pcd [8, 4096, 3] fp32, k = 5)
#define NB 8
#define NPTS 4096
#define KNN 5
#define TPB 128

// --------------------------------------------------------------------------
// Kernel 1: per-point kNN (k=5) -> covariance trace.
// One CTA handles TPB query points of one batch. The whole batch's points are
// staged in dynamic shared memory as float4(x, y, z, |p|^2) = 64 KB.
// Selection key: key_j = |p_j|^2 - 2 * <p_i, p_j>  (monotone in d^2 for fixed i;
// strict '<' displacement reproduces top_k's lowest-index tie-break).
// --------------------------------------------------------------------------
__global__ __launch_bounds__(TPB) void knn_trace_kernel(
    const float* __restrict__ pcd, float* __restrict__ out)
{
    extern __shared__ float4 pts[];  // NPTS float4

    const int chunks_per_b = NPTS / TPB;           // 32
    const int b     = blockIdx.x / chunks_per_b;
    const int chunk = blockIdx.x % chunks_per_b;

    const float* base = pcd + (size_t)b * NPTS * 3;

    // Stage batch tile into smem with precomputed squared norms.
    for (int p = threadIdx.x; p < NPTS; p += TPB) {
        float x = base[p * 3 + 0];
        float y = base[p * 3 + 1];
        float z = base[p * 3 + 2];
        pts[p] = make_float4(x, y, z, fmaf(x, x, fmaf(y, y, z * z)));
    }
    __syncthreads();

    const int qi = chunk * TPB + threadIdx.x;
    const float4 q = pts[qi];
    const float nx = -2.0f * q.x;
    const float ny = -2.0f * q.y;
    const float nz = -2.0f * q.z;

    // Register-resident sorted top-5 (ascending keys). No dynamic indexing.
    float bk[KNN];
    int   bi[KNN];
#pragma unroll
    for (int i = 0; i < KNN; i++) { bk[i] = 3.4e38f; bi[i] = 0; }

#pragma unroll 8
    for (int j = 0; j < NPTS; j++) {
        float4 p = pts[j];                       // warp-uniform -> smem broadcast
        float key = fmaf(p.x, nx, fmaf(p.y, ny, fmaf(p.z, nz, p.w)));
        if (key < bk[KNN - 1]) {                 // rare after warm-up
            bool lt0 = key < bk[0];
            bool lt1 = key < bk[1];
            bool lt2 = key < bk[2];
            bool lt3 = key < bk[3];
            // slot 4
            { float nk = lt3 ? bk[3] : key; int ni = lt3 ? bi[3] : j;
              bk[4] = nk; bi[4] = ni; }
            if (lt3) { float nk = lt2 ? bk[2] : key; int ni = lt2 ? bi[2] : j;
                       bk[3] = nk; bi[3] = ni; }
            if (lt2) { float nk = lt1 ? bk[1] : key; int ni = lt1 ? bi[1] : j;
                       bk[2] = nk; bi[2] = ni; }
            if (lt1) { float nk = lt0 ? bk[0] : key; int ni = lt0 ? bi[0] : j;
                       bk[1] = nk; bi[1] = ni; }
            if (lt0) { bk[0] = key; bi[0] = j; }
        }
    }

    // Gather the 5 neighbor coordinates and compute trace of the 3x3 covariance.
    float4 n0 = pts[bi[0]];
    float4 n1 = pts[bi[1]];
    float4 n2 = pts[bi[2]];
    float4 n3 = pts[bi[3]];
    float4 n4 = pts[bi[4]];

    const float inv_k = 1.0f / (float)KNN;
    float mx = (n0.x + n1.x + n2.x + n3.x + n4.x) * inv_k;
    float my = (n0.y + n1.y + n2.y + n3.y + n4.y) * inv_k;
    float mz = (n0.z + n1.z + n2.z + n3.z + n4.z) * inv_k;

    float tr = 0.0f;
    {
        float dx, dy, dz;
        dx = n0.x - mx; dy = n0.y - my; dz = n0.z - mz;
        tr = fmaf(dx, dx, fmaf(dy, dy, fmaf(dz, dz, tr)));
        dx = n1.x - mx; dy = n1.y - my; dz = n1.z - mz;
        tr = fmaf(dx, dx, fmaf(dy, dy, fmaf(dz, dz, tr)));
        dx = n2.x - mx; dy = n2.y - my; dz = n2.z - mz;
        tr = fmaf(dx, dx, fmaf(dy, dy, fmaf(dz, dz, tr)));
        dx = n3.x - mx; dy = n3.y - my; dz = n3.z - mz;
        tr = fmaf(dx, dx, fmaf(dy, dy, fmaf(dz, dz, tr)));
        dx = n4.x - mx; dy = n4.y - my; dz = n4.z - mz;
        tr = fmaf(dx, dx, fmaf(dy, dy, fmaf(dz, dz, tr)));
    }
    tr *= 1.0f / (float)(KNN - 1);

    out[(size_t)b * NPTS + qi] = tr;
}

// --------------------------------------------------------------------------
// Kernel 2: per-batch normalize: out[b, i] = trace[b, i] / (sum_i trace + 1e-8)
// One CTA per batch; deterministic reduction (fixed shuffle/smem tree).
// --------------------------------------------------------------------------
__global__ __launch_bounds__(256) void finalize_kernel(float* __restrict__ out)
{
    __shared__ float warp_sums[8];
    float* o = out + (size_t)blockIdx.x * NPTS;

    float s = 0.0f;
    for (int i = threadIdx.x; i < NPTS; i += blockDim.x) s += o[i];

#pragma unroll
    for (int off = 16; off > 0; off >>= 1)
        s += __shfl_down_sync(0xffffffffu, s, off);
    if ((threadIdx.x & 31) == 0) warp_sums[threadIdx.x >> 5] = s;
    __syncthreads();

    if (threadIdx.x < 32) {
        float v = (threadIdx.x < (blockDim.x >> 5)) ? warp_sums[threadIdx.x] : 0.0f;
#pragma unroll
        for (int off = 4; off > 0; off >>= 1)
            v += __shfl_down_sync(0xffffffffu, v, off);
        if (threadIdx.x == 0) warp_sums[0] = v;
    }
    __syncthreads();

    const float inv = 1.0f / (warp_sums[0] + 1e-8f);
    for (int i = threadIdx.x; i < NPTS; i += blockDim.x) o[i] *= inv;
}

extern "C" void kernel_launch(void* const* d_in, const int* in_sizes, int n_in,
                              void* d_out, int out_size)
{
    const float* pcd = (const float*)d_in[0];
    float* out = (float*)d_out;

    static bool attr_set = false;  // idempotent host-side attribute, not state-dependent work
    const int smem_bytes = NPTS * (int)sizeof(float4);  // 64 KB
    if (!attr_set) {
        cudaFuncSetAttribute(knn_trace_kernel,
                             cudaFuncAttributeMaxDynamicSharedMemorySize, smem_bytes);
        attr_set = true;
    }

    const int grid = NB * (NPTS / TPB);   // 256 CTAs
    knn_trace_kernel<<<grid, TPB, smem_bytes>>>(pcd, out);
    finalize_kernel<<<NB, 256>>>(out);
}

// round 2
// speedup vs baseline: 1.1095x; 1.1095x over previous
#include <cuda_runtime.h>

// Problem constants (fixed by the dataset: pcd [8, 4096, 3] fp32, k = 5)
#define NB 8
#define NPTS 4096
#define KNN 5
#define NHALF 2048
#define TPB 128
#define CHUNKS (NPTS / TPB)   // 32 query chunks per batch

// Scratch for per-half top-5 candidates (allocation-free rule -> __device__ globals)
__device__ float g_key[2][NB * NPTS * KNN];
__device__ int   g_idx[2][NB * NPTS * KNN];

// --------------------------------------------------------------------------
// Kernel A: per-(query, point-half) top-5 scan.
// CTA = 128 queries x one half of the points (2048). Half tile staged in
// 32KB smem as float4(x,y,z,|p|^2). Software-pipelined (depth 4) so the
// shared loads for group j+4 issue BEFORE the insert branches of group j.
// key_j = |p_j|^2 - 2 q.p_j  (monotone in d^2; strict '<' displacement
// keeps the lowest index on ties, matching jax.lax.top_k).
// --------------------------------------------------------------------------
__global__ __launch_bounds__(TPB) void knn_scan_kernel(const float* __restrict__ pcd)
{
    __shared__ float4 sh[NHALF + 4];     // +4 pad for prefetch overrun

    const int half  = blockIdx.x & 1;
    const int chunk = (blockIdx.x >> 1) % CHUNKS;
    const int b     = blockIdx.x / (2 * CHUNKS);

    const float* base = pcd + (size_t)b * NPTS * 3;
    const int p0 = half * NHALF;

    // Stage this half's points with precomputed squared norms.
    for (int p = threadIdx.x; p < NHALF; p += TPB) {
        float x = base[(p0 + p) * 3 + 0];
        float y = base[(p0 + p) * 3 + 1];
        float z = base[(p0 + p) * 3 + 2];
        sh[p] = make_float4(x, y, z, fmaf(x, x, fmaf(y, y, z * z)));
    }
    if (threadIdx.x < 4)
        sh[NHALF + threadIdx.x] = make_float4(0.f, 0.f, 0.f, 3.0e38f);
    __syncthreads();

    const int qi = chunk * TPB + threadIdx.x;
    const float qx = base[qi * 3 + 0];
    const float qy = base[qi * 3 + 1];
    const float qz = base[qi * 3 + 2];
    const float nx = -2.0f * qx, ny = -2.0f * qy, nz = -2.0f * qz;

    // Register-resident sorted top-5 (ascending). Scalars -> no dyn indexing.
    float bk0 = 3.4e38f, bk1 = 3.4e38f, bk2 = 3.4e38f, bk3 = 3.4e38f, bk4 = 3.4e38f;
    int   bi0 = 0, bi1 = 0, bi2 = 0, bi3 = 0, bi4 = 0;

#define PROC(P, JIDX)                                                         \
    {                                                                         \
        float key = fmaf((P).x, nx, fmaf((P).y, ny, fmaf((P).z, nz, (P).w))); \
        if (key < bk4) {                                                      \
            bool lt0 = key < bk0;                                             \
            bool lt1 = key < bk1;                                             \
            bool lt2 = key < bk2;                                             \
            bool lt3 = key < bk3;                                             \
            bk4 = lt3 ? bk3 : key;  bi4 = lt3 ? bi3 : (JIDX);                 \
            if (lt3) { bk3 = lt2 ? bk2 : key;  bi3 = lt2 ? bi2 : (JIDX); }    \
            if (lt2) { bk2 = lt1 ? bk1 : key;  bi2 = lt1 ? bi1 : (JIDX); }    \
            if (lt1) { bk1 = lt0 ? bk0 : key;  bi1 = lt0 ? bi0 : (JIDX); }    \
            if (lt0) { bk0 = key;              bi0 = (JIDX); }                \
        }                                                                     \
    }

    float4 pA = sh[0], pB = sh[1], pC = sh[2], pD = sh[3];
    for (int j = 0; j < NHALF; j += 4) {
        // Prefetch next group before any branch of this group.
        float4 nA = sh[j + 4];
        float4 nB = sh[j + 5];
        float4 nC = sh[j + 6];
        float4 nD = sh[j + 7];
        PROC(pA, p0 + j + 0);
        PROC(pB, p0 + j + 1);
        PROC(pC, p0 + j + 2);
        PROC(pD, p0 + j + 3);
        pA = nA; pB = nB; pC = nC; pD = nD;
    }
#undef PROC

    const size_t o = ((size_t)b * NPTS + qi) * KNN;
    g_key[half][o + 0] = bk0;  g_idx[half][o + 0] = bi0;
    g_key[half][o + 1] = bk1;  g_idx[half][o + 1] = bi1;
    g_key[half][o + 2] = bk2;  g_idx[half][o + 2] = bi2;
    g_key[half][o + 3] = bk3;  g_idx[half][o + 3] = bi3;
    g_key[half][o + 4] = bk4;  g_idx[half][o + 4] = bi4;
}

// --------------------------------------------------------------------------
// Kernel B: merge the two sorted 5-lists per query (rank counting; half0 /
// lower index wins ties via '<' vs '<='), gather the 5 neighbor coordinates
// from global (pcd is L2-resident), compute trace of the 3x3 covariance with
// the reference's centroid-then-centered numerics.
// --------------------------------------------------------------------------
__global__ __launch_bounds__(256) void merge_trace_kernel(
    const float* __restrict__ pcd, float* __restrict__ out)
{
    const int t = blockIdx.x * 256 + threadIdx.x;   // 0 .. NB*NPTS-1
    const int b = t >> 12;

    float ak[KNN], ck[KNN];
    int   ai[KNN], ci[KNN];
    const size_t o = (size_t)t * KNN;
#pragma unroll
    for (int i = 0; i < KNN; i++) {
        ak[i] = g_key[0][o + i];  ai[i] = g_idx[0][o + i];
        ck[i] = g_key[1][o + i];  ci[i] = g_idx[1][o + i];
    }

    // Selection flags by global rank among the 10 candidates.
    float w[2 * KNN];
#pragma unroll
    for (int i = 0; i < KNN; i++) {
        int r = i;
#pragma unroll
        for (int j = 0; j < KNN; j++) r += (ck[j] < ak[i]);   // half1 precedes half0 only if strictly smaller
        w[i] = (r < KNN) ? 1.0f : 0.0f;
    }
#pragma unroll
    for (int j = 0; j < KNN; j++) {
        int r = j;
#pragma unroll
        for (int i = 0; i < KNN; i++) r += (ak[i] <= ck[j]);  // half0 precedes half1 on ties
        w[KNN + j] = (r < KNN) ? 1.0f : 0.0f;
    }

    // Gather all 10 candidate coordinates (5 are used).
    const float* base = pcd + (size_t)b * NPTS * 3;
    float px[2 * KNN], py[2 * KNN], pz[2 * KNN];
#pragma unroll
    for (int c = 0; c < 2 * KNN; c++) {
        int idx = (c < KNN) ? ai[c] : ci[c - KNN];
        px[c] = base[idx * 3 + 0];
        py[c] = base[idx * 3 + 1];
        pz[c] = base[idx * 3 + 2];
    }

    float sx = 0.f, sy = 0.f, sz = 0.f;
#pragma unroll
    for (int c = 0; c < 2 * KNN; c++) {
        sx = fmaf(w[c], px[c], sx);
        sy = fmaf(w[c], py[c], sy);
        sz = fmaf(w[c], pz[c], sz);
    }
    const float inv_k = 1.0f / (float)KNN;
    const float mx = sx * inv_k, my = sy * inv_k, mz = sz * inv_k;

    float tr = 0.f;
#pragma unroll
    for (int c = 0; c < 2 * KNN; c++) {
        float dx = px[c] - mx, dy = py[c] - my, dz = pz[c] - mz;
        tr = fmaf(w[c], fmaf(dx, dx, fmaf(dy, dy, dz * dz)), tr);
    }
    out[t] = tr * (1.0f / (float)(KNN - 1));
}

// --------------------------------------------------------------------------
// Kernel C: per-batch normalize: out[b,i] = tr[b,i] / (sum_i tr + 1e-8)
// --------------------------------------------------------------------------
__global__ __launch_bounds__(256) void finalize_kernel(float* __restrict__ out)
{
    __shared__ float warp_sums[8];
    float* o = out + (size_t)blockIdx.x * NPTS;

    float s = 0.0f;
    for (int i = threadIdx.x; i < NPTS; i += blockDim.x) s += o[i];

#pragma unroll
    for (int off = 16; off > 0; off >>= 1)
        s += __shfl_down_sync(0xffffffffu, s, off);
    if ((threadIdx.x & 31) == 0) warp_sums[threadIdx.x >> 5] = s;
    __syncthreads();

    if (threadIdx.x < 32) {
        float v = (threadIdx.x < (blockDim.x >> 5)) ? warp_sums[threadIdx.x] : 0.0f;
#pragma unroll
        for (int off = 4; off > 0; off >>= 1)
            v += __shfl_down_sync(0xffffffffu, v, off);
        if (threadIdx.x == 0) warp_sums[0] = v;
    }
    __syncthreads();

    const float inv = 1.0f / (warp_sums[0] + 1e-8f);
    for (int i = threadIdx.x; i < NPTS; i += blockDim.x) o[i] *= inv;
}

extern "C" void kernel_launch(void* const* d_in, const int* in_sizes, int n_in,
                              void* d_out, int out_size)
{
    const float* pcd = (const float*)d_in[0];
    float* out = (float*)d_out;

    knn_scan_kernel<<<NB * CHUNKS * 2, TPB>>>(pcd);
    merge_trace_kernel<<<(NB * NPTS) / 256, 256>>>(pcd, out);
    finalize_kernel<<<NB, 256>>>(out);
}